// round 11
// baseline (speedup 1.0000x reference)
#include <cuda_runtime.h>
#include <cuda_fp16.h>
#include <cstdint>

// Problem constants
#define NNODES 30000
#define NEDGES 100000
#define HH 8
#define DKH 64

// ---------------- device scratch ----------------
__device__ float  g_q   [2][(size_t)NNODES * 512];   // q projections (fp32) per rel
__device__ float  g_kvt [2][(size_t)NNODES * 1024];  // [kt|vt] per rel (fp32)
__device__ __half g_th  [2][(size_t)NNODES * 512];   // aggregated messages fp16 per rel
__device__ __half g_hp_h[(size_t)NNODES * 512];      // h_paper fp16
__device__ __half g_ha_h[(size_t)NNODES * 512];      // h_author fp16
__device__ __half g_WfT2[2][1024 * 512];             // folded transposed fp16 per rel
__device__ __half g_WqT2[2][512 * 512];
__device__ __half g_WaT2[2][512 * 512];
__device__ float  g_bf2 [2][1024];
__device__ int    g_deg [2][NNODES];
__device__ int    g_off [2][NNODES + 1];
__device__ int    g_cur [2][NNODES];
__device__ int    g_el  [2][NEDGES];

// ---------------- helpers ----------------
__device__ __forceinline__ uint32_t smem_u32(const void* p) {
    uint32_t a;
    asm("{ .reg .u64 t; cvta.to.shared.u64 t, %1; cvt.u32.u64 %0, t; }" : "=r"(a) : "l"(p));
    return a;
}
__device__ __forceinline__ void ldmx4(uint32_t* r, uint32_t addr) {
    asm volatile("ldmatrix.sync.aligned.m8n8.x4.shared.b16 {%0,%1,%2,%3}, [%4];"
        : "=r"(r[0]), "=r"(r[1]), "=r"(r[2]), "=r"(r[3]) : "r"(addr));
}
__device__ __forceinline__ void mma_f16(float* c, const uint32_t* a, const uint32_t* b) {
    asm volatile(
        "mma.sync.aligned.m16n8k16.row.col.f32.f16.f16.f32 "
        "{%0,%1,%2,%3}, {%4,%5,%6,%7}, {%8,%9}, {%0,%1,%2,%3};"
        : "+f"(c[0]), "+f"(c[1]), "+f"(c[2]), "+f"(c[3])
        : "r"(a[0]), "r"(a[1]), "r"(a[2]), "r"(a[3]), "r"(b[0]), "r"(b[1]));
}
__device__ __forceinline__ void cp16(uint32_t dst, const void* src) {
    asm volatile("cp.async.cg.shared.global [%0], [%1], 16;" :: "r"(dst), "l"(src));
}
#define CP_COMMIT() asm volatile("cp.async.commit_group;")
#define CP_WAIT1()  asm volatile("cp.async.wait_group 1;")

// ---------------- fp32 -> fp16 convert ----------------
__global__ void f2h_kernel(const float* __restrict__ in, __half* __restrict__ out, int n8)
{
    int i = blockIdx.x * blockDim.x + threadIdx.x;
    if (i >= n8) return;
    const float4* p = (const float4*)in + 2 * (size_t)i;
    float4 a = p[0], b = p[1];
    __half2 h0 = __floats2half2_rn(a.x, a.y);
    __half2 h1 = __floats2half2_rn(a.z, a.w);
    __half2 h2 = __floats2half2_rn(b.x, b.y);
    __half2 h3 = __floats2half2_rn(b.z, b.w);
    *(uint4*)(out + 8 * (size_t)i) =
        make_uint4(*(uint32_t*)&h0, *(uint32_t*)&h1, *(uint32_t*)&h2, *(uint32_t*)&h3);
}

// ---------------- fold kernel (batched over rel via z) ----------------
struct FoldP {
    const float* Wk[2]; const float* bk[2];
    const float* Wv[2]; const float* bv[2];
    const float* Ar[2]; const float* Mr[2];
    __half* WfT[2]; float* bf[2];
};
__global__ void fold_k(FoldP p)
{
    int rel = blockIdx.z;
    int j = blockIdx.x * blockDim.x + threadIdx.x;   // 0..1023
    int i = blockIdx.y;                              // 0..512 (512 == bias row)
    const float* T;
    int jj;
    const float* Wrow;
    if (j < 512) { T = p.Ar[rel]; jj = j; }
    else         { T = p.Mr[rel]; jj = j - 512; }
    int h = jj >> 6, d = jj & 63;
    if (i < 512) Wrow = (j < 512 ? p.Wk[rel] : p.Wv[rel]) + (size_t)i * 512 + h * 64;
    else         Wrow = (j < 512 ? p.bk[rel] : p.bv[rel]) + h * 64;
    const float* Tcol = T + (size_t)h * 64 * 64 + d;
    float s = 0.f;
#pragma unroll 8
    for (int k = 0; k < 64; k++) s += Wrow[k] * Tcol[k * 64];
    if (i < 512) p.WfT[rel][(size_t)j * 512 + i] = __float2half_rn(s);
    else         p.bf[rel][j] = s;
}

// ---------------- transpose 512x512 fp32 -> fp16 (batched over 4 via z) ----------------
struct TrP { const float* W[4]; __half* WT[4]; };
__global__ void transpose_k(TrP p)
{
    __shared__ float t[32][33];
    const float* W = p.W[blockIdx.z];
    __half* WT = p.WT[blockIdx.z];
    int x = blockIdx.x * 32 + threadIdx.x;
    int y = blockIdx.y * 32 + threadIdx.y;
#pragma unroll
    for (int r = 0; r < 32; r += 8)
        t[threadIdx.y + r][threadIdx.x] = W[(size_t)(y + r) * 512 + x];
    __syncthreads();
    int x2 = blockIdx.y * 32 + threadIdx.x;
    int y2 = blockIdx.x * 32 + threadIdx.y;
#pragma unroll
    for (int r = 0; r < 32; r += 8)
        WT[(size_t)(y2 + r) * 512 + x2] = __float2half_rn(t[threadIdx.x][threadIdx.y + r]);
}

// ---------------- shared GEMM mainloop ----------------
// C[m0:,n0:+256] = Ah[M,512] @ BT[.,512]^T + bias (+ optional blend)
template<bool BLEND>
__device__ __forceinline__ void gemm_body(
    const __half* __restrict__ Ah, const __half* __restrict__ BT,
    const float* __restrict__ bias, float* __restrict__ C,
    const float* __restrict__ Hres, float alpha, float beta,
    int M, int LDC, int m0, int n0, __half* sm)
{
    constexpr int AOFF  = 0;
    constexpr int BOFF  = 128 * 40;
    constexpr int STAGE = 128 * 40 + 256 * 40;

    const int tid = threadIdx.x;
    const int wid = tid >> 5, lane = tid & 31;
    const int wm = wid & 1, wn = wid >> 1;
    const int g = lane >> 2, t = lane & 3;
    const uint32_t sb = smem_u32(sm);

    const int arow = tid & 127;
    const int aseg = (tid >> 7) * 2;
    int gar = m0 + arow; if (gar >= M) gar = M - 1;
    const __half* Asrc = Ah + (size_t)gar * 512 + aseg * 8;
    const __half* Bsrc = BT + (size_t)(n0 + tid) * 512;
    const uint32_t a_dst0 = sb + (uint32_t)(AOFF + arow * 40 + aseg * 8) * 2;
    const uint32_t b_dst0 = sb + (uint32_t)(BOFF + tid * 40) * 2;

    const int a_lm = (wm * 64 + (lane & 15)) * 40 + ((lane >> 4) << 3);
    const int b_lm = (wn * 64 + ((lane >> 4) << 3) + (lane & 7)) * 40 + (((lane >> 3) & 1) << 3);

    float acc[4][8][4];
#pragma unroll
    for (int i = 0; i < 4; i++)
#pragma unroll
        for (int j = 0; j < 8; j++)
#pragma unroll
            for (int r = 0; r < 4; r++) acc[i][j][r] = 0.f;

#pragma unroll
    for (int s = 0; s < 2; s++) {
        const int k0 = s * 32;
        const uint32_t so = (uint32_t)(s * STAGE) * 2;
        cp16(a_dst0 + so,      Asrc + k0);
        cp16(a_dst0 + so + 16, Asrc + k0 + 8);
#pragma unroll
        for (int u = 0; u < 4; u++)
            cp16(b_dst0 + so + u * 16, Bsrc + k0 + u * 8);
        CP_COMMIT();
    }

    for (int it = 0; it < 16; ++it) {
        const int buf = it % 3;
        CP_WAIT1();
        __syncthreads();

        if (it + 2 < 16) {
            const int ps = (it + 2) % 3;
            const int k0 = (it + 2) * 32;
            const uint32_t so = (uint32_t)(ps * STAGE) * 2;
            cp16(a_dst0 + so,      Asrc + k0);
            cp16(a_dst0 + so + 16, Asrc + k0 + 8);
#pragma unroll
            for (int u = 0; u < 4; u++)
                cp16(b_dst0 + so + u * 16, Bsrc + k0 + u * 8);
        }
        CP_COMMIT();

        const uint32_t ab = sb + (uint32_t)(buf * STAGE) * 2;
        const uint32_t bb = ab + (uint32_t)BOFF * 2;
#pragma unroll
        for (int s = 0; s < 2; s++) {
            uint32_t a[4][4], b[4][4];
#pragma unroll
            for (int i = 0; i < 4; i++)
                ldmx4(a[i], ab + (uint32_t)(a_lm + i * 16 * 40 + s * 16) * 2);
#pragma unroll
            for (int jp = 0; jp < 4; jp++)
                ldmx4(b[jp], bb + (uint32_t)(b_lm + jp * 16 * 40 + s * 16) * 2);
#pragma unroll
            for (int i = 0; i < 4; i++)
#pragma unroll
                for (int j = 0; j < 8; j++)
                    mma_f16(acc[i][j], a[i], &b[j >> 1][(j & 1) * 2]);
        }
    }

#pragma unroll
    for (int i = 0; i < 4; i++) {
        int row = m0 + wm * 64 + i * 16 + g;
#pragma unroll
        for (int j = 0; j < 8; j++) {
            int col = n0 + wn * 64 + j * 8 + 2 * t;
            float2 bv = *(const float2*)(bias + col);
#pragma unroll
            for (int half = 0; half < 2; half++) {
                int r = row + half * 8;
                if (r < M) {
                    float2 o;
                    o.x = acc[i][j][half * 2 + 0] + bv.x;
                    o.y = acc[i][j][half * 2 + 1] + bv.y;
                    if (BLEND) {
                        float2 hv = *(const float2*)(Hres + (size_t)r * LDC + col);
                        o.x = o.x * alpha + hv.x * beta;
                        o.y = o.y * alpha + hv.y * beta;
                    }
                    *(float2*)(C + (size_t)r * LDC + col) = o;
                }
            }
        }
    }
}

// ---------------- batched projection GEMM: kvt (x<4) and q (x>=4), z = rel ----------------
struct ProjP {
    const __half* A[2][2];
    const __half* B[2][2];
    const float*  bias[2][2];
    float*        C[2][2];
    int M;
};
__global__ __launch_bounds__(256) void proj_gemm(ProjP p)
{
    extern __shared__ __half sm[];
    int rel = blockIdx.z;
    int xs = blockIdx.x;
    int which = xs >= 4 ? 1 : 0;
    int n0 = (which ? xs - 4 : xs) * 256;
    int LDC = which ? 512 : 1024;
    gemm_body<false>(p.A[rel][which], p.B[rel][which], p.bias[rel][which],
                     p.C[rel][which], nullptr, 1.f, 0.f, p.M, LDC,
                     blockIdx.y * 128, n0, sm);
}

// ---------------- batched output GEMM with blend, z = rel ----------------
struct OutP {
    const __half* A[2]; const __half* B[2]; const float* bias[2];
    float* C[2]; const float* Hres[2]; const float* skip; int M;
};
__global__ __launch_bounds__(256) void out_gemm(OutP p)
{
    extern __shared__ __half sm[];
    int rel = blockIdx.z;
    float s = p.skip[rel];
    float alpha = 1.f / (1.f + __expf(-s));
    gemm_body<true>(p.A[rel], p.B[rel], p.bias[rel], p.C[rel], p.Hres[rel],
                    alpha, 1.f - alpha, p.M, 512, blockIdx.y * 128, blockIdx.x * 256, sm);
}

// ---------------- CSR build ----------------
struct CsrP {
    const int* dst[2]; const int* srcp[2];
    int* deg[2]; int* off[2]; int* cursor[2]; int* elist[2];
    int E; int N;
};
__global__ void hist_k(CsrP p)
{
    int rel = blockIdx.y;
    int i = blockIdx.x * 256 + threadIdx.x;
    if (i < p.E) atomicAdd(&p.deg[rel][p.dst[rel][i]], 1);
}
__global__ void scan_k(CsrP p)
{
    int rel = blockIdx.y;
    const int* deg = p.deg[rel];
    int* off = p.off[rel];
    const int n = p.N;
    const int T = 1024;
    int tid = threadIdx.x;
    int chunk = (n + T - 1) / T;
    int lo = tid * chunk, hi = lo + chunk; if (hi > n) hi = n; if (lo > n) lo = n;
    int s = 0;
    for (int i = lo; i < hi; i++) s += deg[i];
    __shared__ int ps[1024];
    ps[tid] = s;
    __syncthreads();
    for (int d = 1; d < 1024; d <<= 1) {
        int v = (tid >= d) ? ps[tid - d] : 0;
        __syncthreads();
        ps[tid] += v;
        __syncthreads();
    }
    int run = ps[tid] - s;
    for (int i = lo; i < hi; i++) { off[i] = run; run += deg[i]; }
    if (tid == T - 1) off[n] = run;
}
__global__ void fill_k(CsrP p)
{
    int rel = blockIdx.y;
    int i = blockIdx.x * 256 + threadIdx.x;
    if (i < p.E) {
        int d = p.dst[rel][i];
        int pos = atomicAdd(&p.cursor[rel][d], 1);
        p.elist[rel][pos] = p.srcp[rel][i];
    }
}

// ---------------- fused edge aggregation: online softmax, warp per dst ----------------
struct EdgeP {
    const float* q[2]; const float* kvt[2];
    const int* off[2]; const int* elist[2];
    const float* pri;
    __half* th[2];
    int N;
};
__global__ __launch_bounds__(256) void edge_agg(EdgeP p)
{
    int rel = blockIdx.y;
    int wid = threadIdx.x >> 5, lane = threadIdx.x & 31;
    int d = blockIdx.x * 8 + wid;
    if (d >= p.N) return;
    int h = lane >> 2;
    float prih = p.pri[rel * 8 + h] * 0.125f;

    const float4* qp = (const float4*)(p.q[rel] + (size_t)d * 512 + lane * 16);
    float4 q0 = qp[0], q1 = qp[1], q2 = qp[2], q3 = qp[3];

    float m = -1e30f, ss = 0.f;
    float acc[16];
#pragma unroll
    for (int i = 0; i < 16; i++) acc[i] = 0.f;

    const int beg = p.off[rel][d], end = p.off[rel][d + 1];
    const float* kvt = p.kvt[rel];
    const int* el = p.elist[rel];

    for (int idx = beg; idx < end; ++idx) {
        int s = el[idx];
        const float4* kp = (const float4*)(kvt + (size_t)s * 1024 + lane * 16);
        float4 k0 = kp[0], k1 = kp[1], k2 = kp[2], k3 = kp[3];
        const float4* vp = (const float4*)(kvt + (size_t)s * 1024 + 512 + lane * 16);
        float4 v0 = vp[0], v1 = vp[1], v2 = vp[2], v3 = vp[3];

        float dot = q0.x * k0.x + q0.y * k0.y + q0.z * k0.z + q0.w * k0.w
                  + q1.x * k1.x + q1.y * k1.y + q1.z * k1.z + q1.w * k1.w
                  + q2.x * k2.x + q2.y * k2.y + q2.z * k2.z + q2.w * k2.w
                  + q3.x * k3.x + q3.y * k3.y + q3.z * k3.z + q3.w * k3.w;
        dot += __shfl_xor_sync(0xffffffffu, dot, 1);
        dot += __shfl_xor_sync(0xffffffffu, dot, 2);
        float a = dot * prih;

        float nm = fmaxf(m, a);
        float sc = __expf(m - nm);
        float w  = __expf(a - nm);
        m = nm;
        ss = ss * sc + w;
        acc[0]  = acc[0]  * sc + w * v0.x;  acc[1]  = acc[1]  * sc + w * v0.y;
        acc[2]  = acc[2]  * sc + w * v0.z;  acc[3]  = acc[3]  * sc + w * v0.w;
        acc[4]  = acc[4]  * sc + w * v1.x;  acc[5]  = acc[5]  * sc + w * v1.y;
        acc[6]  = acc[6]  * sc + w * v1.z;  acc[7]  = acc[7]  * sc + w * v1.w;
        acc[8]  = acc[8]  * sc + w * v2.x;  acc[9]  = acc[9]  * sc + w * v2.y;
        acc[10] = acc[10] * sc + w * v2.z;  acc[11] = acc[11] * sc + w * v2.w;
        acc[12] = acc[12] * sc + w * v3.x;  acc[13] = acc[13] * sc + w * v3.y;
        acc[14] = acc[14] * sc + w * v3.z;  acc[15] = acc[15] * sc + w * v3.w;
    }

    float inv = ss > 0.f ? 1.f / ss : 0.f;
    uint32_t o[8];
#pragma unroll
    for (int j = 0; j < 8; j++) {
        __half2 hh = __floats2half2_rn(acc[2 * j] * inv, acc[2 * j + 1] * inv);
        o[j] = *(uint32_t*)&hh;
    }
    uint4* dst = (uint4*)(p.th[rel] + (size_t)d * 512 + lane * 16);
    dst[0] = make_uint4(o[0], o[1], o[2], o[3]);
    dst[1] = make_uint4(o[4], o[5], o[6], o[7]);
}

// ---------------- host launcher ----------------
extern "C" void kernel_launch(void* const* d_in, const int* in_sizes, int n_in,
                              void* d_out, int out_size)
{
    const float* h_paper  = (const float*)d_in[0];
    const float* h_author = (const float*)d_in[1];
    const int*   src0     = (const int*)d_in[2];
    const int*   dst0     = (const int*)d_in[3];
    const int*   src1     = (const int*)d_in[4];
    const int*   dst1     = (const int*)d_in[5];
    const float* Wk0 = (const float*)d_in[6];  const float* bk0 = (const float*)d_in[7];
    const float* Wq0 = (const float*)d_in[8];  const float* bq0 = (const float*)d_in[9];
    const float* Wv0 = (const float*)d_in[10]; const float* bv0 = (const float*)d_in[11];
    const float* Wa0 = (const float*)d_in[12]; const float* ba0 = (const float*)d_in[13];
    const float* Wk1 = (const float*)d_in[14]; const float* bk1 = (const float*)d_in[15];
    const float* Wq1 = (const float*)d_in[16]; const float* bq1 = (const float*)d_in[17];
    const float* Wv1 = (const float*)d_in[18]; const float* bv1 = (const float*)d_in[19];
    const float* Wa1 = (const float*)d_in[20]; const float* ba1 = (const float*)d_in[21];
    const float* rel_att = (const float*)d_in[22];
    const float* rel_msg = (const float*)d_in[23];
    const float* rel_pri = (const float*)d_in[24];
    const float* skip    = (const float*)d_in[25];

    const int N = in_sizes[0] / 512;
    const int E = in_sizes[2];
    float* out = (float*)d_out;

    // resolve scratch
    void *pq, *pkvt, *pth, *php, *pha, *pwf, *pwq, *pwa, *pbf, *pdeg, *poff, *pcur, *pel;
    cudaGetSymbolAddress(&pq,   g_q);
    cudaGetSymbolAddress(&pkvt, g_kvt);
    cudaGetSymbolAddress(&pth,  g_th);
    cudaGetSymbolAddress(&php,  g_hp_h);
    cudaGetSymbolAddress(&pha,  g_ha_h);
    cudaGetSymbolAddress(&pwf,  g_WfT2);
    cudaGetSymbolAddress(&pwq,  g_WqT2);
    cudaGetSymbolAddress(&pwa,  g_WaT2);
    cudaGetSymbolAddress(&pbf,  g_bf2);
    cudaGetSymbolAddress(&pdeg, g_deg);
    cudaGetSymbolAddress(&poff, g_off);
    cudaGetSymbolAddress(&pcur, g_cur);
    cudaGetSymbolAddress(&pel,  g_el);
    float*  qb[2]  = { (float*)pq,            (float*)pq  + (size_t)NNODES * 512 };
    float*  kv[2]  = { (float*)pkvt,          (float*)pkvt + (size_t)NNODES * 1024 };
    __half* th[2]  = { (__half*)pth,          (__half*)pth + (size_t)NNODES * 512 };
    __half* hp_h   = (__half*)php;
    __half* ha_h   = (__half*)pha;
    __half* wf[2]  = { (__half*)pwf,          (__half*)pwf + 1024 * 512 };
    __half* wq[2]  = { (__half*)pwq,          (__half*)pwq + 512 * 512 };
    __half* wa[2]  = { (__half*)pwa,          (__half*)pwa + 512 * 512 };
    float*  bfp[2] = { (float*)pbf,           (float*)pbf + 1024 };
    int*    deg[2] = { (int*)pdeg,            (int*)pdeg + NNODES };
    int*    off[2] = { (int*)poff,            (int*)poff + NNODES + 1 };
    int*    cur[2] = { (int*)pcur,            (int*)pcur + NNODES };
    int*    el[2]  = { (int*)pel,             (int*)pel + NEDGES };

    const int SMEM_SZ = 3 * (128 * 40 + 256 * 40) * 2;  // 92160 bytes
    cudaFuncSetAttribute(proj_gemm, cudaFuncAttributeMaxDynamicSharedMemorySize, SMEM_SZ);
    cudaFuncSetAttribute(out_gemm,  cudaFuncAttributeMaxDynamicSharedMemorySize, SMEM_SZ);

    const int gm = (N + 127) / 128;
    const int n8 = N * 512 / 8;
    const int relT = HH * DKH * DKH;

    // 1) fp16 node features
    f2h_kernel<<<(n8 + 255) / 256, 256>>>(h_paper,  hp_h, n8);
    f2h_kernel<<<(n8 + 255) / 256, 256>>>(h_author, ha_h, n8);

    // 2) fold + transposes (batched)
    {
        FoldP fp;
        fp.Wk[0] = Wk1; fp.bk[0] = bk1; fp.Wv[0] = Wv1; fp.bv[0] = bv1;
        fp.Wk[1] = Wk0; fp.bk[1] = bk0; fp.Wv[1] = Wv0; fp.bv[1] = bv0;
        fp.Ar[0] = rel_att;        fp.Mr[0] = rel_msg;
        fp.Ar[1] = rel_att + relT; fp.Mr[1] = rel_msg + relT;
        fp.WfT[0] = wf[0]; fp.WfT[1] = wf[1];
        fp.bf[0] = bfp[0]; fp.bf[1] = bfp[1];
        fold_k<<<dim3(4, 513, 2), 256>>>(fp);

        TrP tp;
        tp.W[0] = Wq0; tp.WT[0] = wq[0];
        tp.W[1] = Wq1; tp.WT[1] = wq[1];
        tp.W[2] = Wa0; tp.WT[2] = wa[0];
        tp.W[3] = Wa1; tp.WT[3] = wa[1];
        transpose_k<<<dim3(16, 16, 4), dim3(32, 8)>>>(tp);
    }

    // 3) CSR build (both relations)
    {
        cudaMemsetAsync(deg[0], 0, NNODES * sizeof(int));
        cudaMemsetAsync(deg[1], 0, NNODES * sizeof(int));
        CsrP cp;
        cp.dst[0] = dst0; cp.srcp[0] = src0;
        cp.dst[1] = dst1; cp.srcp[1] = src1;
        for (int r = 0; r < 2; r++) { cp.deg[r] = deg[r]; cp.off[r] = off[r]; cp.cursor[r] = cur[r]; cp.elist[r] = el[r]; }
        cp.E = E; cp.N = N;
        hist_k<<<dim3((E + 255) / 256, 2), 256>>>(cp);
        scan_k<<<dim3(1, 2), 1024>>>(cp);
        cudaMemcpyAsync(cur[0], off[0], NNODES * sizeof(int), cudaMemcpyDeviceToDevice);
        cudaMemcpyAsync(cur[1], off[1], NNODES * sizeof(int), cudaMemcpyDeviceToDevice);
        fill_k<<<dim3((E + 255) / 256, 2), 256>>>(cp);
    }

    // 4) projection GEMMs: kvt + q for both relations, one launch
    {
        ProjP pp;
        // rel0: src=author, dst=paper ; rel1: src=paper, dst=author
        pp.A[0][0] = ha_h; pp.A[0][1] = hp_h;
        pp.A[1][0] = hp_h; pp.A[1][1] = ha_h;
        pp.B[0][0] = wf[0]; pp.B[0][1] = wq[0];
        pp.B[1][0] = wf[1]; pp.B[1][1] = wq[1];
        pp.bias[0][0] = bfp[0]; pp.bias[0][1] = bq0;
        pp.bias[1][0] = bfp[1]; pp.bias[1][1] = bq1;
        pp.C[0][0] = kv[0]; pp.C[0][1] = qb[0];
        pp.C[1][0] = kv[1]; pp.C[1][1] = qb[1];
        pp.M = N;
        proj_gemm<<<dim3(6, gm, 2), 256, SMEM_SZ>>>(pp);
    }

    // 5) fused edge aggregation (online softmax), both relations
    {
        EdgeP ep;
        ep.q[0] = qb[0]; ep.q[1] = qb[1];
        ep.kvt[0] = kv[0]; ep.kvt[1] = kv[1];
        ep.off[0] = off[0]; ep.off[1] = off[1];
        ep.elist[0] = el[0]; ep.elist[1] = el[1];
        ep.pri = rel_pri;
        ep.th[0] = th[0]; ep.th[1] = th[1];
        ep.N = N;
        edge_agg<<<dim3((N + 7) / 8, 2), 256>>>(ep);
    }

    // 6) output GEMMs with sigmoid-skip blend, both relations
    {
        OutP op;
        op.A[0] = th[0]; op.A[1] = th[1];
        op.B[0] = wa[0]; op.B[1] = wa[1];
        op.bias[0] = ba0; op.bias[1] = ba1;
        op.C[0] = out;   op.C[1] = out + (size_t)N * 512;
        op.Hres[0] = h_paper; op.Hres[1] = h_author;
        op.skip = skip;
        op.M = N;
        out_gemm<<<dim3(2, gm, 2), 256, SMEM_SZ>>>(op);
    }
}

// round 12
// speedup vs baseline: 1.0016x; 1.0016x over previous
#include <cuda_runtime.h>
#include <cuda_fp16.h>
#include <cstdint>

// Problem constants
#define NNODES 30000
#define NEDGES 100000
#define HH 8
#define DKH 64

// ---------------- device scratch ----------------
__device__ float  g_q   [2][(size_t)NNODES * 512];   // q projections (fp32) per rel
__device__ float  g_kvt [2][(size_t)NNODES * 1024];  // [kt|vt] per rel (fp32)
__device__ __half g_th  [2][(size_t)NNODES * 512];   // aggregated messages fp16 per rel
__device__ __half g_hp_h[(size_t)NNODES * 512];      // h_paper fp16
__device__ __half g_ha_h[(size_t)NNODES * 512];      // h_author fp16
__device__ __half g_WfT2[2][1024 * 512];             // folded transposed fp16 per rel
__device__ __half g_WqT2[2][512 * 512];
__device__ __half g_WaT2[2][512 * 512];
__device__ float  g_bf2 [2][1024];
__device__ int    g_deg [2][NNODES];
__device__ int    g_off [2][NNODES + 1];
__device__ int    g_cur [2][NNODES];
__device__ int    g_el  [2][NEDGES];

// ---------------- helpers ----------------
__device__ __forceinline__ uint32_t smem_u32(const void* p) {
    uint32_t a;
    asm("{ .reg .u64 t; cvta.to.shared.u64 t, %1; cvt.u32.u64 %0, t; }" : "=r"(a) : "l"(p));
    return a;
}
__device__ __forceinline__ void ldmx4(uint32_t* r, uint32_t addr) {
    asm volatile("ldmatrix.sync.aligned.m8n8.x4.shared.b16 {%0,%1,%2,%3}, [%4];"
        : "=r"(r[0]), "=r"(r[1]), "=r"(r[2]), "=r"(r[3]) : "r"(addr));
}
__device__ __forceinline__ void mma_f16(float* c, const uint32_t* a, const uint32_t* b) {
    asm volatile(
        "mma.sync.aligned.m16n8k16.row.col.f32.f16.f16.f32 "
        "{%0,%1,%2,%3}, {%4,%5,%6,%7}, {%8,%9}, {%0,%1,%2,%3};"
        : "+f"(c[0]), "+f"(c[1]), "+f"(c[2]), "+f"(c[3])
        : "r"(a[0]), "r"(a[1]), "r"(a[2]), "r"(a[3]), "r"(b[0]), "r"(b[1]));
}
__device__ __forceinline__ void cp16(uint32_t dst, const void* src) {
    asm volatile("cp.async.cg.shared.global [%0], [%1], 16;" :: "r"(dst), "l"(src));
}
#define CP_COMMIT() asm volatile("cp.async.commit_group;")
#define CP_WAIT1()  asm volatile("cp.async.wait_group 1;")

// ---------------- fp32 -> fp16 convert ----------------
__global__ void f2h_kernel(const float* __restrict__ in, __half* __restrict__ out, int n8)
{
    int i = blockIdx.x * blockDim.x + threadIdx.x;
    if (i >= n8) return;
    const float4* p = (const float4*)in + 2 * (size_t)i;
    float4 a = p[0], b = p[1];
    __half2 h0 = __floats2half2_rn(a.x, a.y);
    __half2 h1 = __floats2half2_rn(a.z, a.w);
    __half2 h2 = __floats2half2_rn(b.x, b.y);
    __half2 h3 = __floats2half2_rn(b.z, b.w);
    *(uint4*)(out + 8 * (size_t)i) =
        make_uint4(*(uint32_t*)&h0, *(uint32_t*)&h1, *(uint32_t*)&h2, *(uint32_t*)&h3);
}

// ---------------- fold kernel (batched over rel via z) ----------------
struct FoldP {
    const float* Wk[2]; const float* bk[2];
    const float* Wv[2]; const float* bv[2];
    const float* Ar[2]; const float* Mr[2];
    __half* WfT[2]; float* bf[2];
};
__global__ void fold_k(FoldP p)
{
    int rel = blockIdx.z;
    int j = blockIdx.x * blockDim.x + threadIdx.x;   // 0..1023
    int i = blockIdx.y;                              // 0..512 (512 == bias row)
    const float* T;
    int jj;
    const float* Wrow;
    if (j < 512) { T = p.Ar[rel]; jj = j; }
    else         { T = p.Mr[rel]; jj = j - 512; }
    int h = jj >> 6, d = jj & 63;
    if (i < 512) Wrow = (j < 512 ? p.Wk[rel] : p.Wv[rel]) + (size_t)i * 512 + h * 64;
    else         Wrow = (j < 512 ? p.bk[rel] : p.bv[rel]) + h * 64;
    const float* Tcol = T + (size_t)h * 64 * 64 + d;
    float s = 0.f;
#pragma unroll 8
    for (int k = 0; k < 64; k++) s += Wrow[k] * Tcol[k * 64];
    if (i < 512) p.WfT[rel][(size_t)j * 512 + i] = __float2half_rn(s);
    else         p.bf[rel][j] = s;
}

// ---------------- transpose 512x512 fp32 -> fp16 (batched over 4 via z) ----------------
struct TrP { const float* W[4]; __half* WT[4]; };
__global__ void transpose_k(TrP p)
{
    __shared__ float t[32][33];
    const float* W = p.W[blockIdx.z];
    __half* WT = p.WT[blockIdx.z];
    int x = blockIdx.x * 32 + threadIdx.x;
    int y = blockIdx.y * 32 + threadIdx.y;
#pragma unroll
    for (int r = 0; r < 32; r += 8)
        t[threadIdx.y + r][threadIdx.x] = W[(size_t)(y + r) * 512 + x];
    __syncthreads();
    int x2 = blockIdx.y * 32 + threadIdx.x;
    int y2 = blockIdx.x * 32 + threadIdx.y;
#pragma unroll
    for (int r = 0; r < 32; r += 8)
        WT[(size_t)(y2 + r) * 512 + x2] = __float2half_rn(t[threadIdx.x][threadIdx.y + r]);
}

// ---------------- shared GEMM mainloop ----------------
// C[m0:,n0:+256] = Ah[M,512] @ BT[.,512]^T + bias (+ optional blend)
template<bool BLEND>
__device__ __forceinline__ void gemm_body(
    const __half* __restrict__ Ah, const __half* __restrict__ BT,
    const float* __restrict__ bias, float* __restrict__ C,
    const float* __restrict__ Hres, float alpha, float beta,
    int M, int LDC, int m0, int n0, __half* sm)
{
    constexpr int AOFF  = 0;
    constexpr int BOFF  = 128 * 40;
    constexpr int STAGE = 128 * 40 + 256 * 40;

    const int tid = threadIdx.x;
    const int wid = tid >> 5, lane = tid & 31;
    const int wm = wid & 1, wn = wid >> 1;
    const int g = lane >> 2, t = lane & 3;
    const uint32_t sb = smem_u32(sm);

    const int arow = tid & 127;
    const int aseg = (tid >> 7) * 2;
    int gar = m0 + arow; if (gar >= M) gar = M - 1;
    const __half* Asrc = Ah + (size_t)gar * 512 + aseg * 8;
    const __half* Bsrc = BT + (size_t)(n0 + tid) * 512;
    const uint32_t a_dst0 = sb + (uint32_t)(AOFF + arow * 40 + aseg * 8) * 2;
    const uint32_t b_dst0 = sb + (uint32_t)(BOFF + tid * 40) * 2;

    const int a_lm = (wm * 64 + (lane & 15)) * 40 + ((lane >> 4) << 3);
    const int b_lm = (wn * 64 + ((lane >> 4) << 3) + (lane & 7)) * 40 + (((lane >> 3) & 1) << 3);

    float acc[4][8][4];
#pragma unroll
    for (int i = 0; i < 4; i++)
#pragma unroll
        for (int j = 0; j < 8; j++)
#pragma unroll
            for (int r = 0; r < 4; r++) acc[i][j][r] = 0.f;

#pragma unroll
    for (int s = 0; s < 2; s++) {
        const int k0 = s * 32;
        const uint32_t so = (uint32_t)(s * STAGE) * 2;
        cp16(a_dst0 + so,      Asrc + k0);
        cp16(a_dst0 + so + 16, Asrc + k0 + 8);
#pragma unroll
        for (int u = 0; u < 4; u++)
            cp16(b_dst0 + so + u * 16, Bsrc + k0 + u * 8);
        CP_COMMIT();
    }

    for (int it = 0; it < 16; ++it) {
        const int buf = it % 3;
        CP_WAIT1();
        __syncthreads();

        if (it + 2 < 16) {
            const int ps = (it + 2) % 3;
            const int k0 = (it + 2) * 32;
            const uint32_t so = (uint32_t)(ps * STAGE) * 2;
            cp16(a_dst0 + so,      Asrc + k0);
            cp16(a_dst0 + so + 16, Asrc + k0 + 8);
#pragma unroll
            for (int u = 0; u < 4; u++)
                cp16(b_dst0 + so + u * 16, Bsrc + k0 + u * 8);
        }
        CP_COMMIT();

        const uint32_t ab = sb + (uint32_t)(buf * STAGE) * 2;
        const uint32_t bb = ab + (uint32_t)BOFF * 2;
#pragma unroll
        for (int s = 0; s < 2; s++) {
            uint32_t a[4][4], b[4][4];
#pragma unroll
            for (int i = 0; i < 4; i++)
                ldmx4(a[i], ab + (uint32_t)(a_lm + i * 16 * 40 + s * 16) * 2);
#pragma unroll
            for (int jp = 0; jp < 4; jp++)
                ldmx4(b[jp], bb + (uint32_t)(b_lm + jp * 16 * 40 + s * 16) * 2);
#pragma unroll
            for (int i = 0; i < 4; i++)
#pragma unroll
                for (int j = 0; j < 8; j++)
                    mma_f16(acc[i][j], a[i], &b[j >> 1][(j & 1) * 2]);
        }
    }

#pragma unroll
    for (int i = 0; i < 4; i++) {
        int row = m0 + wm * 64 + i * 16 + g;
#pragma unroll
        for (int j = 0; j < 8; j++) {
            int col = n0 + wn * 64 + j * 8 + 2 * t;
            float2 bv = *(const float2*)(bias + col);
#pragma unroll
            for (int half = 0; half < 2; half++) {
                int r = row + half * 8;
                if (r < M) {
                    float2 o;
                    o.x = acc[i][j][half * 2 + 0] + bv.x;
                    o.y = acc[i][j][half * 2 + 1] + bv.y;
                    if (BLEND) {
                        float2 hv = *(const float2*)(Hres + (size_t)r * LDC + col);
                        o.x = o.x * alpha + hv.x * beta;
                        o.y = o.y * alpha + hv.y * beta;
                    }
                    *(float2*)(C + (size_t)r * LDC + col) = o;
                }
            }
        }
    }
}

// ---------------- batched projection GEMM: kvt (x<4) and q (x>=4), z = rel ----------------
struct ProjP {
    const __half* A[2][2];
    const __half* B[2][2];
    const float*  bias[2][2];
    float*        C[2][2];
    int M;
};
__global__ __launch_bounds__(256) void proj_gemm(ProjP p)
{
    extern __shared__ __half sm[];
    int rel = blockIdx.z;
    int xs = blockIdx.x;
    int which = xs >= 4 ? 1 : 0;
    int n0 = (which ? xs - 4 : xs) * 256;
    int LDC = which ? 512 : 1024;
    gemm_body<false>(p.A[rel][which], p.B[rel][which], p.bias[rel][which],
                     p.C[rel][which], nullptr, 1.f, 0.f, p.M, LDC,
                     blockIdx.y * 128, n0, sm);
}

// ---------------- batched output GEMM with blend, z = rel ----------------
struct OutP {
    const __half* A[2]; const __half* B[2]; const float* bias[2];
    float* C[2]; const float* Hres[2]; const float* skip; int M;
};
__global__ __launch_bounds__(256) void out_gemm(OutP p)
{
    extern __shared__ __half sm[];
    int rel = blockIdx.z;
    float s = p.skip[rel];
    float alpha = 1.f / (1.f + __expf(-s));
    gemm_body<true>(p.A[rel], p.B[rel], p.bias[rel], p.C[rel], p.Hres[rel],
                    alpha, 1.f - alpha, p.M, 512, blockIdx.y * 128, blockIdx.x * 256, sm);
}

// ---------------- CSR build ----------------
struct CsrP {
    const int* dst[2]; const int* srcp[2];
    int* deg[2]; int* off[2]; int* cursor[2]; int* elist[2];
    int E; int N;
};
__global__ void hist_k(CsrP p)
{
    int rel = blockIdx.y;
    int i = blockIdx.x * 256 + threadIdx.x;
    if (i < p.E) atomicAdd(&p.deg[rel][p.dst[rel][i]], 1);
}
__global__ void scan_k(CsrP p)
{
    int rel = blockIdx.y;
    const int* deg = p.deg[rel];
    int* off = p.off[rel];
    const int n = p.N;
    const int T = 1024;
    int tid = threadIdx.x;
    int chunk = (n + T - 1) / T;
    int lo = tid * chunk, hi = lo + chunk; if (hi > n) hi = n; if (lo > n) lo = n;
    int s = 0;
    for (int i = lo; i < hi; i++) s += deg[i];
    __shared__ int ps[1024];
    ps[tid] = s;
    __syncthreads();
    for (int d = 1; d < 1024; d <<= 1) {
        int v = (tid >= d) ? ps[tid - d] : 0;
        __syncthreads();
        ps[tid] += v;
        __syncthreads();
    }
    int run = ps[tid] - s;
    for (int i = lo; i < hi; i++) { off[i] = run; run += deg[i]; }
    if (tid == T - 1) off[n] = run;
}
__global__ void fill_k(CsrP p)
{
    int rel = blockIdx.y;
    int i = blockIdx.x * 256 + threadIdx.x;
    if (i < p.E) {
        int d = p.dst[rel][i];
        int pos = atomicAdd(&p.cursor[rel][d], 1);
        p.elist[rel][pos] = p.srcp[rel][i];
    }
}

// ---------------- fused edge aggregation: online softmax, warp per dst ----------------
struct EdgeP {
    const float* q[2]; const float* kvt[2];
    const int* off[2]; const int* elist[2];
    const float* pri;
    __half* th[2];
    int N;
};
__global__ __launch_bounds__(256) void edge_agg(EdgeP p)
{
    int rel = blockIdx.y;
    int wid = threadIdx.x >> 5, lane = threadIdx.x & 31;
    int d = blockIdx.x * 8 + wid;
    if (d >= p.N) return;
    int h = lane >> 2;
    float prih = p.pri[rel * 8 + h] * 0.125f;

    const float4* qp = (const float4*)(p.q[rel] + (size_t)d * 512 + lane * 16);
    float4 q0 = qp[0], q1 = qp[1], q2 = qp[2], q3 = qp[3];

    float m = -1e30f, ss = 0.f;
    float acc[16];
#pragma unroll
    for (int i = 0; i < 16; i++) acc[i] = 0.f;

    const int beg = p.off[rel][d], end = p.off[rel][d + 1];
    const float* kvt = p.kvt[rel];
    const int* el = p.elist[rel];

    for (int idx = beg; idx < end; ++idx) {
        int s = el[idx];
        const float4* kp = (const float4*)(kvt + (size_t)s * 1024 + lane * 16);
        float4 k0 = kp[0], k1 = kp[1], k2 = kp[2], k3 = kp[3];
        const float4* vp = (const float4*)(kvt + (size_t)s * 1024 + 512 + lane * 16);
        float4 v0 = vp[0], v1 = vp[1], v2 = vp[2], v3 = vp[3];

        float dot = q0.x * k0.x + q0.y * k0.y + q0.z * k0.z + q0.w * k0.w
                  + q1.x * k1.x + q1.y * k1.y + q1.z * k1.z + q1.w * k1.w
                  + q2.x * k2.x + q2.y * k2.y + q2.z * k2.z + q2.w * k2.w
                  + q3.x * k3.x + q3.y * k3.y + q3.z * k3.z + q3.w * k3.w;
        dot += __shfl_xor_sync(0xffffffffu, dot, 1);
        dot += __shfl_xor_sync(0xffffffffu, dot, 2);
        float a = dot * prih;

        float nm = fmaxf(m, a);
        float sc = __expf(m - nm);
        float w  = __expf(a - nm);
        m = nm;
        ss = ss * sc + w;
        acc[0]  = acc[0]  * sc + w * v0.x;  acc[1]  = acc[1]  * sc + w * v0.y;
        acc[2]  = acc[2]  * sc + w * v0.z;  acc[3]  = acc[3]  * sc + w * v0.w;
        acc[4]  = acc[4]  * sc + w * v1.x;  acc[5]  = acc[5]  * sc + w * v1.y;
        acc[6]  = acc[6]  * sc + w * v1.z;  acc[7]  = acc[7]  * sc + w * v1.w;
        acc[8]  = acc[8]  * sc + w * v2.x;  acc[9]  = acc[9]  * sc + w * v2.y;
        acc[10] = acc[10] * sc + w * v2.z;  acc[11] = acc[11] * sc + w * v2.w;
        acc[12] = acc[12] * sc + w * v3.x;  acc[13] = acc[13] * sc + w * v3.y;
        acc[14] = acc[14] * sc + w * v3.z;  acc[15] = acc[15] * sc + w * v3.w;
    }

    float inv = ss > 0.f ? 1.f / ss : 0.f;
    uint32_t o[8];
#pragma unroll
    for (int j = 0; j < 8; j++) {
        __half2 hh = __floats2half2_rn(acc[2 * j] * inv, acc[2 * j + 1] * inv);
        o[j] = *(uint32_t*)&hh;
    }
    uint4* dst = (uint4*)(p.th[rel] + (size_t)d * 512 + lane * 16);
    dst[0] = make_uint4(o[0], o[1], o[2], o[3]);
    dst[1] = make_uint4(o[4], o[5], o[6], o[7]);
}

// ---------------- host launcher ----------------
extern "C" void kernel_launch(void* const* d_in, const int* in_sizes, int n_in,
                              void* d_out, int out_size)
{
    const float* h_paper  = (const float*)d_in[0];
    const float* h_author = (const float*)d_in[1];
    const int*   src0     = (const int*)d_in[2];
    const int*   dst0     = (const int*)d_in[3];
    const int*   src1     = (const int*)d_in[4];
    const int*   dst1     = (const int*)d_in[5];
    const float* Wk0 = (const float*)d_in[6];  const float* bk0 = (const float*)d_in[7];
    const float* Wq0 = (const float*)d_in[8];  const float* bq0 = (const float*)d_in[9];
    const float* Wv0 = (const float*)d_in[10]; const float* bv0 = (const float*)d_in[11];
    const float* Wa0 = (const float*)d_in[12]; const float* ba0 = (const float*)d_in[13];
    const float* Wk1 = (const float*)d_in[14]; const float* bk1 = (const float*)d_in[15];
    const float* Wq1 = (const float*)d_in[16]; const float* bq1 = (const float*)d_in[17];
    const float* Wv1 = (const float*)d_in[18]; const float* bv1 = (const float*)d_in[19];
    const float* Wa1 = (const float*)d_in[20]; const float* ba1 = (const float*)d_in[21];
    const float* rel_att = (const float*)d_in[22];
    const float* rel_msg = (const float*)d_in[23];
    const float* rel_pri = (const float*)d_in[24];
    const float* skip    = (const float*)d_in[25];

    const int N = in_sizes[0] / 512;
    const int E = in_sizes[2];
    float* out = (float*)d_out;

    // resolve scratch
    void *pq, *pkvt, *pth, *php, *pha, *pwf, *pwq, *pwa, *pbf, *pdeg, *poff, *pcur, *pel;
    cudaGetSymbolAddress(&pq,   g_q);
    cudaGetSymbolAddress(&pkvt, g_kvt);
    cudaGetSymbolAddress(&pth,  g_th);
    cudaGetSymbolAddress(&php,  g_hp_h);
    cudaGetSymbolAddress(&pha,  g_ha_h);
    cudaGetSymbolAddress(&pwf,  g_WfT2);
    cudaGetSymbolAddress(&pwq,  g_WqT2);
    cudaGetSymbolAddress(&pwa,  g_WaT2);
    cudaGetSymbolAddress(&pbf,  g_bf2);
    cudaGetSymbolAddress(&pdeg, g_deg);
    cudaGetSymbolAddress(&poff, g_off);
    cudaGetSymbolAddress(&pcur, g_cur);
    cudaGetSymbolAddress(&pel,  g_el);
    float*  qb[2]  = { (float*)pq,            (float*)pq  + (size_t)NNODES * 512 };
    float*  kv[2]  = { (float*)pkvt,          (float*)pkvt + (size_t)NNODES * 1024 };
    __half* th[2]  = { (__half*)pth,          (__half*)pth + (size_t)NNODES * 512 };
    __half* hp_h   = (__half*)php;
    __half* ha_h   = (__half*)pha;
    __half* wf[2]  = { (__half*)pwf,          (__half*)pwf + 1024 * 512 };
    __half* wq[2]  = { (__half*)pwq,          (__half*)pwq + 512 * 512 };
    __half* wa[2]  = { (__half*)pwa,          (__half*)pwa + 512 * 512 };
    float*  bfp[2] = { (float*)pbf,           (float*)pbf + 1024 };
    int*    deg[2] = { (int*)pdeg,            (int*)pdeg + NNODES };
    int*    off[2] = { (int*)poff,            (int*)poff + NNODES + 1 };
    int*    cur[2] = { (int*)pcur,            (int*)pcur + NNODES };
    int*    el[2]  = { (int*)pel,             (int*)pel + NEDGES };

    const int SMEM_SZ = 3 * (128 * 40 + 256 * 40) * 2;  // 92160 bytes
    cudaFuncSetAttribute(proj_gemm, cudaFuncAttributeMaxDynamicSharedMemorySize, SMEM_SZ);
    cudaFuncSetAttribute(out_gemm,  cudaFuncAttributeMaxDynamicSharedMemorySize, SMEM_SZ);

    const int gm = (N + 127) / 128;
    const int n8 = N * 512 / 8;
    const int relT = HH * DKH * DKH;

    // 1) fp16 node features
    f2h_kernel<<<(n8 + 255) / 256, 256>>>(h_paper,  hp_h, n8);
    f2h_kernel<<<(n8 + 255) / 256, 256>>>(h_author, ha_h, n8);

    // 2) fold + transposes (batched)
    {
        FoldP fp;
        fp.Wk[0] = Wk1; fp.bk[0] = bk1; fp.Wv[0] = Wv1; fp.bv[0] = bv1;
        fp.Wk[1] = Wk0; fp.bk[1] = bk0; fp.Wv[1] = Wv0; fp.bv[1] = bv0;
        fp.Ar[0] = rel_att;        fp.Mr[0] = rel_msg;
        fp.Ar[1] = rel_att + relT; fp.Mr[1] = rel_msg + relT;
        fp.WfT[0] = wf[0]; fp.WfT[1] = wf[1];
        fp.bf[0] = bfp[0]; fp.bf[1] = bfp[1];
        fold_k<<<dim3(4, 513, 2), 256>>>(fp);

        TrP tp;
        tp.W[0] = Wq0; tp.WT[0] = wq[0];
        tp.W[1] = Wq1; tp.WT[1] = wq[1];
        tp.W[2] = Wa0; tp.WT[2] = wa[0];
        tp.W[3] = Wa1; tp.WT[3] = wa[1];
        transpose_k<<<dim3(16, 16, 4), dim3(32, 8)>>>(tp);
    }

    // 3) CSR build (both relations)
    {
        cudaMemsetAsync(deg[0], 0, NNODES * sizeof(int));
        cudaMemsetAsync(deg[1], 0, NNODES * sizeof(int));
        CsrP cp;
        cp.dst[0] = dst0; cp.srcp[0] = src0;
        cp.dst[1] = dst1; cp.srcp[1] = src1;
        for (int r = 0; r < 2; r++) { cp.deg[r] = deg[r]; cp.off[r] = off[r]; cp.cursor[r] = cur[r]; cp.elist[r] = el[r]; }
        cp.E = E; cp.N = N;
        hist_k<<<dim3((E + 255) / 256, 2), 256>>>(cp);
        scan_k<<<dim3(1, 2), 1024>>>(cp);
        cudaMemcpyAsync(cur[0], off[0], NNODES * sizeof(int), cudaMemcpyDeviceToDevice);
        cudaMemcpyAsync(cur[1], off[1], NNODES * sizeof(int), cudaMemcpyDeviceToDevice);
        fill_k<<<dim3((E + 255) / 256, 2), 256>>>(cp);
    }

    // 4) projection GEMMs: kvt + q for both relations, one launch
    {
        ProjP pp;
        // rel0: src=author, dst=paper ; rel1: src=paper, dst=author
        pp.A[0][0] = ha_h; pp.A[0][1] = hp_h;
        pp.A[1][0] = hp_h; pp.A[1][1] = ha_h;
        pp.B[0][0] = wf[0]; pp.B[0][1] = wq[0];
        pp.B[1][0] = wf[1]; pp.B[1][1] = wq[1];
        pp.bias[0][0] = bfp[0]; pp.bias[0][1] = bq0;
        pp.bias[1][0] = bfp[1]; pp.bias[1][1] = bq1;
        pp.C[0][0] = kv[0]; pp.C[0][1] = qb[0];
        pp.C[1][0] = kv[1]; pp.C[1][1] = qb[1];
        pp.M = N;
        proj_gemm<<<dim3(6, gm, 2), 256, SMEM_SZ>>>(pp);
    }

    // 5) fused edge aggregation (online softmax), both relations
    {
        EdgeP ep;
        ep.q[0] = qb[0]; ep.q[1] = qb[1];
        ep.kvt[0] = kv[0]; ep.kvt[1] = kv[1];
        ep.off[0] = off[0]; ep.off[1] = off[1];
        ep.elist[0] = el[0]; ep.elist[1] = el[1];
        ep.pri = rel_pri;
        ep.th[0] = th[0]; ep.th[1] = th[1];
        ep.N = N;
        edge_agg<<<dim3((N + 7) / 8, 2), 256>>>(ep);
    }

    // 6) output GEMMs with sigmoid-skip blend, both relations
    {
        OutP op;
        op.A[0] = th[0]; op.A[1] = th[1];
        op.B[0] = wa[0]; op.B[1] = wa[1];
        op.bias[0] = ba0; op.bias[1] = ba1;
        op.C[0] = out;   op.C[1] = out + (size_t)N * 512;
        op.Hres[0] = h_paper; op.Hres[1] = h_author;
        op.skip = skip;
        op.M = N;
        out_gemm<<<dim3(2, gm, 2), 256, SMEM_SZ>>>(op);
    }
}